// round 6
// baseline (speedup 1.0000x reference)
#include <cuda_runtime.h>

#define NPIX 65536      // B*H*W = 64*32*32
#define DDIM 256
#define KCODES 512
#define MT 32           // pixels per CTA
#define KT 128          // codes per K-chunk
#define DCHUNK 8        // d per streamed chunk (2 x float4 halves)
#define ZS_STRIDE 260   // 256+4 floats; 1040B row stride = 65*16B (aligned)
#define THREADS 128
#define NDC (DDIM / DCHUNK)   // 32 d-chunks
#define NKC (KCODES / KT)     // 4 k-chunks
#define TCH (NKC * NDC)       // 128 total chunks
// e-tile chunk layout: [d4half (2)][code (128)] x float4  => 1024 floats/chunk
#define EBUF_FLOATS (2 * KT * 4)

__device__ float g_esq[KCODES];

// Packed f32x2 FMA (sm_100+): acc = a*b + acc lane-wise on the 2-float pack.
__device__ __forceinline__ void fma2(unsigned long long& acc,
                                     unsigned long long a,
                                     unsigned long long b) {
    asm("fma.rn.f32x2 %0, %1, %2, %0;" : "+l"(acc) : "l"(a), "l"(b));
}

__global__ void esq_kernel(const float* __restrict__ cb) {
    int k = blockIdx.x * blockDim.x + threadIdx.x;
    if (k >= KCODES) return;
    const float4* row = (const float4*)(cb + k * DDIM);
    float sx = 0.f, sy = 0.f, sz = 0.f, sw = 0.f;
#pragma unroll
    for (int i = 0; i < DDIM / 4; i++) {
        float4 v = row[i];
        sx = __fadd_rn(sx, __fmul_rn(v.x, v.x));
        sy = __fadd_rn(sy, __fmul_rn(v.y, v.y));
        sz = __fadd_rn(sz, __fmul_rn(v.z, v.z));
        sw = __fadd_rn(sw, __fmul_rn(v.w, v.w));
    }
    g_esq[k] = __fadd_rn(__fadd_rn(sx, sy), __fadd_rn(sz, sw));
}

__global__ __launch_bounds__(THREADS, 3)
void vq_argmin_kernel(const float* __restrict__ z,
                      const float* __restrict__ cb,
                      float* __restrict__ out) {
    // Static shared, ~41.6 KB total (< 48 KB, no opt-in)
    __shared__ __align__(16) float z_s[MT * ZS_STRIDE];        // 33,280 B
    __shared__ __align__(16) float e_s[2 * EBUF_FLOATS];       //  8,192 B
    __shared__ float zsq_s[MT];

    const int tid   = threadIdx.x;
    const int c_id  = tid & 15;     // 16 code lanes (x8 codes = 128/k-chunk)
    const int px_id = tid >> 4;     // 8 pixel groups of 4 pixels
    const int pix_base = blockIdx.x * MT;

    // ---- transpose z tile: gmem [b, d, hw] -> z_s[p][d] ----
    {
        const int b   = pix_base >> 10;
        const int hw0 = pix_base & 1023;
        const float* zbase = z + (size_t)b * (DDIM * 1024) + hw0;
#pragma unroll
        for (int it = 0; it < 16; it++) {
            int linear = tid + THREADS * it;      // 0..2047 float4 slots
            int d  = linear >> 3;                 // 0..255
            int p4 = (linear & 7) << 2;           // 0..28
            float4 v = *(const float4*)(zbase + (size_t)d * 1024 + p4);
            z_s[(p4 + 0) * ZS_STRIDE + d] = v.x;
            z_s[(p4 + 1) * ZS_STRIDE + d] = v.y;
            z_s[(p4 + 2) * ZS_STRIDE + d] = v.z;
            z_s[(p4 + 3) * ZS_STRIDE + d] = v.w;
        }
    }
    __syncthreads();

    // ---- per-pixel |z|^2 (square rounded separately, 4-lane pairwise sum) ----
    if (tid < MT) {
        const float4* zr = (const float4*)(z_s + tid * ZS_STRIDE);
        float sx = 0.f, sy = 0.f, sz = 0.f, sw = 0.f;
#pragma unroll
        for (int i = 0; i < DDIM / 4; i++) {
            float4 v = zr[i];
            sx = __fadd_rn(sx, __fmul_rn(v.x, v.x));
            sy = __fadd_rn(sy, __fmul_rn(v.y, v.y));
            sz = __fadd_rn(sz, __fmul_rn(v.z, v.z));
            sw = __fadd_rn(sw, __fmul_rn(v.w, v.w));
        }
        zsq_s[tid] = __fadd_rn(__fadd_rn(sx, sy), __fadd_rn(sz, sw));
    }

    // ---- prefetch chunk 0 (kc=0, dc=0) into buffer 0 ----
    // slot s (0..255): code c = s>>1, d4-half = s&1
    // e-buf word offset = ((half*KT) + c) * 4  -> 16B-consecutive per code
    float4 pf0, pf1;
    {
        int i0 = tid, i1 = tid + THREADS;
        pf0 = *(const float4*)(cb + (size_t)(i0 >> 1) * DDIM + (i0 & 1) * 4);
        pf1 = *(const float4*)(cb + (size_t)(i1 >> 1) * DDIM + (i1 & 1) * 4);
        *(float4*)(e_s + (((i0 & 1) * KT) + (i0 >> 1)) * 4) = pf0;
        *(float4*)(e_s + (((i1 & 1) * KT) + (i1 >> 1)) * 4) = pf1;
    }
    __syncthreads();

    float best[4];
    int   bidx[4];
    unsigned long long acc[4][8];   // [pixel][code] even/odd-d packed sums
#pragma unroll
    for (int i = 0; i < 4; i++) {
        best[i] = 3.4e38f; bidx[i] = 0;
#pragma unroll
        for (int j = 0; j < 8; j++) acc[i][j] = 0ULL;
    }

    for (int t = 0; t < TCH; t++) {
        const int cur = t & 1;
        const int dc  = t & (NDC - 1);

        // issue prefetch of chunk t+1 (L2 latency overlapped with compute)
        if (t + 1 < TCH) {
            const int nk = (t + 1) >> 5;
            const int nd = (t + 1) & (NDC - 1);
            int i0 = tid, i1 = tid + THREADS;
            pf0 = *(const float4*)(cb + (size_t)(nk * KT + (i0 >> 1)) * DDIM +
                                   nd * DCHUNK + (i0 & 1) * 4);
            pf1 = *(const float4*)(cb + (size_t)(nk * KT + (i1 >> 1)) * DDIM +
                                   nd * DCHUNK + (i1 & 1) * 4);
        }

        // compute: 4 pixels x 8 codes x 8 d  (128 FMA2 per chunk)
        const float* zb = z_s + (px_id * 4) * ZS_STRIDE + dc * DCHUNK;
        const float* eb = e_s + cur * EBUF_FLOATS;
#pragma unroll
        for (int d4 = 0; d4 < 2; d4++) {
            ulonglong2 zv[4];
#pragma unroll
            for (int i = 0; i < 4; i++)
                zv[i] = *(const ulonglong2*)(zb + i * ZS_STRIDE + d4 * 4);
#pragma unroll
            for (int j = 0; j < 8; j++) {
                // ev: 16 lanes -> 16 consecutive 16B slots: 2 wavefronts, no conflicts
                ulonglong2 ev = *(const ulonglong2*)(eb + (d4 * KT + c_id + 16 * j) * 4);
#pragma unroll
                for (int i = 0; i < 4; i++) fma2(acc[i][j], zv[i].x, ev.x);
#pragma unroll
                for (int i = 0; i < 4; i++) fma2(acc[i][j], zv[i].y, ev.y);
            }
        }

        // store prefetched chunk into the other buffer
        if (t + 1 < TCH) {
            int i0 = tid, i1 = tid + THREADS;
            float* dst = e_s + (cur ^ 1) * EBUF_FLOATS;
            *(float4*)(dst + (((i0 & 1) * KT) + (i0 >> 1)) * 4) = pf0;
            *(float4*)(dst + (((i1 & 1) * KT) + (i1 >> 1)) * 4) = pf1;
        }
        __syncthreads();

        // end of a K-chunk: fold into running argmin, reset accumulators
        if (dc == NDC - 1) {
            const int kc = t >> 5;
#pragma unroll
            for (int j = 0; j < 8; j++) {
                const int code = kc * KT + c_id + 16 * j;
                const float esq = __ldg(&g_esq[code]);
#pragma unroll
                for (int i = 0; i < 4; i++) {
                    float lo = __uint_as_float((unsigned)(acc[i][j] & 0xffffffffULL));
                    float hi = __uint_as_float((unsigned)(acc[i][j] >> 32));
                    float cross = __fadd_rn(lo, hi);
                    float d = __fadd_rn(__fadd_rn(zsq_s[px_id * 4 + i],
                                                  -2.0f * cross), esq);
                    if (d < best[i]) { best[i] = d; bidx[i] = code; }
                    acc[i][j] = 0ULL;
                }
            }
        }
    }

    // ---- argmin across the 16 code-lanes of each pixel group ----
#pragma unroll
    for (int i = 0; i < 4; i++) {
        float v = best[i];
        int   ix = bidx[i];
#pragma unroll
        for (int off = 8; off >= 1; off >>= 1) {
            float ov = __shfl_xor_sync(0xffffffffu, v, off, 16);
            int   oi = __shfl_xor_sync(0xffffffffu, ix, off, 16);
            if (ov < v || (ov == v && oi < ix)) { v = ov; ix = oi; }
        }
        // Output dtype is float32: indices < 512 exactly representable.
        if (c_id == 0) out[pix_base + px_id * 4 + i] = (float)ix;
    }
}

extern "C" void kernel_launch(void* const* d_in, const int* in_sizes, int n_in,
                              void* d_out, int out_size) {
    // z_e_x: 16,777,216 elems; codebook: 131,072 elems — identify by size.
    const float* a0 = (const float*)d_in[0];
    const float* a1 = (const float*)d_in[1];
    const float* z  = (in_sizes[0] > in_sizes[1]) ? a0 : a1;
    const float* cb = (in_sizes[0] > in_sizes[1]) ? a1 : a0;
    float* out = (float*)d_out;

    esq_kernel<<<2, 256>>>(cb);
    vq_argmin_kernel<<<NPIX / MT, THREADS>>>(z, cb, out);
}